// round 2
// baseline (speedup 1.0000x reference)
#include <cuda_runtime.h>

// y[4096] = x[1,5504] @ W[4096, act_idx[cluster]]^T + bias
// Strategy: scatter x into a dense xs[11008] (atomicAdd for duplicate cols),
// then dense coalesced GEMV y = W @ xs + bias. HBM-bound: streams full 180MB W.
// NOTE: JAX default config disables x64 -> act_idx arrives as int32, cluster as int32.

#define D_OUT 4096
#define D_IN 11008
#define REMAINED 5504
#define ROWS_PER_BLOCK 8
#define THREADS 256

__device__ float g_xs[D_IN];

__global__ void zero_xs_kernel() {
    int i = blockIdx.x * blockDim.x + threadIdx.x;
    if (i < D_IN) g_xs[i] = 0.0f;
}

__global__ void scatter_x_kernel(const float* __restrict__ x,
                                 const int* __restrict__ act_idx,
                                 const int* __restrict__ cluster) {
    int i = blockIdx.x * blockDim.x + threadIdx.x;
    if (i < REMAINED) {
        int cl = *cluster;
        int c = act_idx[cl * REMAINED + i];
        atomicAdd(&g_xs[c], x[i]);
    }
}

__global__ __launch_bounds__(THREADS) void gemv_kernel(
    const float* __restrict__ weight,
    const float* __restrict__ bias,
    float* __restrict__ out)
{
    // Stage xs in shared memory once per block; amortize across 8 rows.
    __shared__ float4 sxs[D_IN / 4];  // 44032 bytes
    const float4* gx4 = reinterpret_cast<const float4*>(g_xs);
    for (int i = threadIdx.x; i < D_IN / 4; i += THREADS)
        sxs[i] = gx4[i];
    __syncthreads();

    const int warp = threadIdx.x >> 5;
    const int lane = threadIdx.x & 31;
    const int row  = blockIdx.x * ROWS_PER_BLOCK + warp;

    const float4* __restrict__ w4 =
        reinterpret_cast<const float4*>(weight + (size_t)row * D_IN);

    float acc = 0.0f;
    // 2752 float4 per row / 32 lanes = 86 iterations, exact.
#pragma unroll 4
    for (int i = lane; i < D_IN / 4; i += 32) {
        float4 a = w4[i];
        float4 b = sxs[i];
        acc = fmaf(a.x, b.x, acc);
        acc = fmaf(a.y, b.y, acc);
        acc = fmaf(a.z, b.z, acc);
        acc = fmaf(a.w, b.w, acc);
    }

#pragma unroll
    for (int off = 16; off > 0; off >>= 1)
        acc += __shfl_xor_sync(0xffffffffu, acc, off);

    if (lane == 0)
        out[row] = acc + bias[row];
}

extern "C" void kernel_launch(void* const* d_in, const int* in_sizes, int n_in,
                              void* d_out, int out_size) {
    const float* x       = (const float*)d_in[0];   // (1, 5504)
    const float* weight  = (const float*)d_in[1];   // (4096, 11008)
    const float* bias    = (const float*)d_in[2];   // (4096,)
    const int*   act_idx = (const int*)d_in[3];     // (64, 5504) int32 (jax x64 off)
    const int*   cluster = (const int*)d_in[4];     // scalar int32
    float*       out     = (float*)d_out;           // (1, 4096)

    zero_xs_kernel<<<(D_IN + 255) / 256, 256>>>();
    scatter_x_kernel<<<(REMAINED + 255) / 256, 256>>>(x, act_idx, cluster);
    gemv_kernel<<<D_OUT / ROWS_PER_BLOCK, THREADS>>>(weight, bias, out);
}

// round 3
// speedup vs baseline: 1.2962x; 1.2962x over previous
#include <cuda_runtime.h>

// y[4096] = x[1,5504] @ W[4096, act_idx[cluster]]^T + bias
// Fully fused: each block builds the densified xs[11008] directly in shared
// memory (zero -> gather x/idx -> smem atomicAdd scatter), then streams its
// 16 W rows with coalesced float4 loads. Single kernel, single wave.

#define D_OUT 4096
#define D_IN 11008
#define REMAINED 5504
#define ROWS_PER_BLOCK 16
#define THREADS 512
#define NBLOCKS (D_OUT / ROWS_PER_BLOCK)   // 256

__global__ __launch_bounds__(THREADS) void fused_gemv_kernel(
    const float* __restrict__ x,
    const float* __restrict__ weight,
    const float* __restrict__ bias,
    const int*   __restrict__ act_idx,
    const int*   __restrict__ cluster,
    float*       __restrict__ out)
{
    __shared__ float sxs[D_IN];  // 44032 bytes

    // 1) zero
    float4* sxs4 = reinterpret_cast<float4*>(sxs);
    #pragma unroll
    for (int i = threadIdx.x; i < D_IN / 4; i += THREADS)
        sxs4[i] = make_float4(0.f, 0.f, 0.f, 0.f);
    __syncthreads();

    // 2) gather x + idx (L2-multicast across blocks), scatter into smem
    const int cl = *cluster;
    const int* idx_row = act_idx + cl * REMAINED;
    #pragma unroll
    for (int i = threadIdx.x; i < REMAINED; i += THREADS) {
        int   c = __ldg(idx_row + i);
        float v = __ldg(x + i);
        atomicAdd(&sxs[c], v);
    }
    __syncthreads();

    // 3) dense GEMV: one warp per row, 16 rows per block
    const int warp = threadIdx.x >> 5;
    const int lane = threadIdx.x & 31;
    const int row  = blockIdx.x * ROWS_PER_BLOCK + warp;

    const float4* __restrict__ w4 =
        reinterpret_cast<const float4*>(weight + (size_t)row * D_IN);
    const float4* sx4 = reinterpret_cast<const float4*>(sxs);

    float acc = 0.0f;
    // 2752 float4 per row / 32 lanes = 86 iterations, exact.
    #pragma unroll 4
    for (int i = lane; i < D_IN / 4; i += 32) {
        float4 a = __ldcs(w4 + i);   // streaming: no reuse of W
        float4 b = sx4[i];
        acc = fmaf(a.x, b.x, acc);
        acc = fmaf(a.y, b.y, acc);
        acc = fmaf(a.z, b.z, acc);
        acc = fmaf(a.w, b.w, acc);
    }

    #pragma unroll
    for (int off = 16; off > 0; off >>= 1)
        acc += __shfl_xor_sync(0xffffffffu, acc, off);

    if (lane == 0)
        out[row] = acc + bias[row];
}

extern "C" void kernel_launch(void* const* d_in, const int* in_sizes, int n_in,
                              void* d_out, int out_size) {
    const float* x       = (const float*)d_in[0];   // (1, 5504)
    const float* weight  = (const float*)d_in[1];   // (4096, 11008)
    const float* bias    = (const float*)d_in[2];   // (4096,)
    const int*   act_idx = (const int*)d_in[3];     // (64, 5504) int32 (jax x64 off)
    const int*   cluster = (const int*)d_in[4];     // scalar int32
    float*       out     = (float*)d_out;           // (1, 4096)

    fused_gemv_kernel<<<NBLOCKS, THREADS>>>(x, weight, bias, act_idx, cluster, out);
}

// round 4
// speedup vs baseline: 1.3773x; 1.0626x over previous
#include <cuda_runtime.h>

// y[4096] = x[1,5504] @ W[4096, act_idx[cluster]]^T + bias
// Fully fused, single perfectly-balanced wave:
//   128 blocks x 1024 threads (32 warps), 32 rows/block, 1 row/warp.
// Each block builds densified xs[11008] in smem (zero -> gather -> smem
// atomicAdd scatter), then streams its 32 W rows with coalesced float4 loads.

#define D_OUT 4096
#define D_IN 11008
#define REMAINED 5504
#define ROWS_PER_BLOCK 32
#define THREADS 1024
#define NBLOCKS (D_OUT / ROWS_PER_BLOCK)   // 128

__global__ __launch_bounds__(THREADS, 1) void fused_gemv_kernel(
    const float* __restrict__ x,
    const float* __restrict__ weight,
    const float* __restrict__ bias,
    const int*   __restrict__ act_idx,
    const int*   __restrict__ cluster,
    float*       __restrict__ out)
{
    __shared__ float sxs[D_IN];  // 44032 bytes

    // 1) zero
    float4* sxs4 = reinterpret_cast<float4*>(sxs);
    #pragma unroll
    for (int i = threadIdx.x; i < D_IN / 4; i += THREADS)
        sxs4[i] = make_float4(0.f, 0.f, 0.f, 0.f);
    __syncthreads();

    // 2) gather x + idx (L2-resident after first readers), scatter into smem
    const int cl = *cluster;
    const int* idx_row = act_idx + cl * REMAINED;
    #pragma unroll
    for (int i = threadIdx.x; i < REMAINED; i += THREADS) {
        int   c = __ldg(idx_row + i);
        float v = __ldg(x + i);
        atomicAdd(&sxs[c], v);
    }
    __syncthreads();

    // 3) dense GEMV: one warp per row, 32 rows per block
    const int warp = threadIdx.x >> 5;
    const int lane = threadIdx.x & 31;
    const int row  = blockIdx.x * ROWS_PER_BLOCK + warp;

    const float4* __restrict__ w4 =
        reinterpret_cast<const float4*>(weight + (size_t)row * D_IN);
    const float4* sx4 = reinterpret_cast<const float4*>(sxs);

    float acc0 = 0.0f, acc1 = 0.0f;
    // 2752 float4 per row / 32 lanes = 86 iterations, exact.
    // Process two strided elements per loop body to double MLP per trip and
    // keep two independent FFMA chains.
    #pragma unroll 2
    for (int i = lane; i < D_IN / 4 - 32; i += 64) {
        float4 a0 = __ldcs(w4 + i);
        float4 a1 = __ldcs(w4 + i + 32);
        float4 b0 = sx4[i];
        float4 b1 = sx4[i + 32];
        acc0 = fmaf(a0.x, b0.x, acc0);
        acc0 = fmaf(a0.y, b0.y, acc0);
        acc0 = fmaf(a0.z, b0.z, acc0);
        acc0 = fmaf(a0.w, b0.w, acc0);
        acc1 = fmaf(a1.x, b1.x, acc1);
        acc1 = fmaf(a1.y, b1.y, acc1);
        acc1 = fmaf(a1.z, b1.z, acc1);
        acc1 = fmaf(a1.w, b1.w, acc1);
    }
    // 86 iterations = 43 pairs; pairs cover i < 2720+lane range fully, but
    // handle any tail generically (D_IN/4 = 2752 = 64*43 exactly, no tail).
    static_assert((D_IN / 4) % 64 == 0, "row must split into warp pair-strides");

    float acc = acc0 + acc1;
    #pragma unroll
    for (int off = 16; off > 0; off >>= 1)
        acc += __shfl_xor_sync(0xffffffffu, acc, off);

    if (lane == 0)
        out[row] = acc + bias[row];
}

extern "C" void kernel_launch(void* const* d_in, const int* in_sizes, int n_in,
                              void* d_out, int out_size) {
    const float* x       = (const float*)d_in[0];   // (1, 5504)
    const float* weight  = (const float*)d_in[1];   // (4096, 11008)
    const float* bias    = (const float*)d_in[2];   // (4096,)
    const int*   act_idx = (const int*)d_in[3];     // (64, 5504) int32 (jax x64 off)
    const int*   cluster = (const int*)d_in[4];     // scalar int32
    float*       out     = (float*)d_out;           // (1, 4096)

    fused_gemv_kernel<<<NBLOCKS, THREADS>>>(x, weight, bias, act_idx, cluster, out);
}